// round 2
// baseline (speedup 1.0000x reference)
#include <cuda_runtime.h>
#include <math.h>

#define S_LEN  2048
#define BATCH  2
#define HID    2048
#define NHEAD  16
#define HDIM   128
#define QKV_N  (3 * HID)          // 6144
#define ROWS   (S_LEN * BATCH)    // 4096

// Scratch (device globals: allocation is forbidden in kernel_launch)
__device__ float g_qkv[(size_t)ROWS * QKV_N];   // [s*B + b, 6144]
__device__ float g_ctx[(size_t)ROWS * HID];     // [s*B + b, 2048]

// ---------------------------------------------------------------------------
// SGEMM: C[m,n] = sum_k A[m,k] * B[n,k]  (+ bias[n])
// A: [M,K] row-major, B: [N,K] row-major (i.e. C = A @ B^T)
// 128x128 block, BK=8, 256 threads, 8x8 per thread.
// M % 128 == 0, N % 128 == 0, K % 8 == 0 (true for all our shapes).
// ---------------------------------------------------------------------------
__global__ __launch_bounds__(256, 2)
void sgemm_nt_kernel(const float* __restrict__ A, const float* __restrict__ B,
                     const float* __restrict__ bias, float* __restrict__ C,
                     int M, int N, int K, int add_bias)
{
    __shared__ float As[8][128];
    __shared__ float Bs[8][128];

    const int tid = threadIdx.x;
    const int tx = tid & 15;
    const int ty = tid >> 4;
    const int m0 = blockIdx.y * 128;
    const int n0 = blockIdx.x * 128;

    float acc[8][8];
#pragma unroll
    for (int i = 0; i < 8; i++)
#pragma unroll
        for (int j = 0; j < 8; j++) acc[i][j] = 0.f;

    const int ldRow = tid >> 1;          // 0..127
    const int ldCol = (tid & 1) * 4;     // 0 or 4
    const float* Ap = A + (size_t)(m0 + ldRow) * K + ldCol;
    const float* Bp = B + (size_t)(n0 + ldRow) * K + ldCol;

    for (int k0 = 0; k0 < K; k0 += 8) {
        float4 av = *(const float4*)(Ap + k0);
        float4 bv = *(const float4*)(Bp + k0);
        As[ldCol + 0][ldRow] = av.x; As[ldCol + 1][ldRow] = av.y;
        As[ldCol + 2][ldRow] = av.z; As[ldCol + 3][ldRow] = av.w;
        Bs[ldCol + 0][ldRow] = bv.x; Bs[ldCol + 1][ldRow] = bv.y;
        Bs[ldCol + 2][ldRow] = bv.z; Bs[ldCol + 3][ldRow] = bv.w;
        __syncthreads();

#pragma unroll
        for (int kk = 0; kk < 8; kk++) {
            float4 a0 = *(const float4*)&As[kk][ty * 8];
            float4 a1 = *(const float4*)&As[kk][ty * 8 + 4];
            float4 b0 = *(const float4*)&Bs[kk][tx * 8];
            float4 b1 = *(const float4*)&Bs[kk][tx * 8 + 4];
            float ar[8] = {a0.x, a0.y, a0.z, a0.w, a1.x, a1.y, a1.z, a1.w};
            float br[8] = {b0.x, b0.y, b0.z, b0.w, b1.x, b1.y, b1.z, b1.w};
#pragma unroll
            for (int i = 0; i < 8; i++)
#pragma unroll
                for (int j = 0; j < 8; j++)
                    acc[i][j] += ar[i] * br[j];
        }
        __syncthreads();
    }

    float bb[8];
#pragma unroll
    for (int j = 0; j < 8; j++)
        bb[j] = add_bias ? bias[n0 + tx * 8 + j] : 0.f;

#pragma unroll
    for (int i = 0; i < 8; i++) {
        const int row = m0 + ty * 8 + i;
        float* Crow = C + (size_t)row * N + n0 + tx * 8;
        float4 r0, r1;
        r0.x = acc[i][0] + bb[0]; r0.y = acc[i][1] + bb[1];
        r0.z = acc[i][2] + bb[2]; r0.w = acc[i][3] + bb[3];
        r1.x = acc[i][4] + bb[4]; r1.y = acc[i][5] + bb[5];
        r1.z = acc[i][6] + bb[6]; r1.w = acc[i][7] + bb[7];
        *(float4*)(Crow + 0) = r0;
        *(float4*)(Crow + 4) = r1;
    }
}

// ---------------------------------------------------------------------------
// Flash-attention (fp32, causal). One CTA per (q-tile=64, head, batch).
// 256 threads as 16x16; thread owns a 4x4 S-subtile and 4x8 O-subtile.
// ---------------------------------------------------------------------------
#define QT 64
#define QS_LD 129
#define PS_LD 65
// floats: Qs 64*129 + Ks 64*129 + Vs 64*128 + Ps 64*65
#define ATTN_SMEM_FLOATS (64 * QS_LD * 2 + 64 * 128 + 64 * PS_LD)
#define ATTN_SMEM_BYTES  (ATTN_SMEM_FLOATS * 4)

__global__ __launch_bounds__(256, 1)
void attn_kernel(const float* __restrict__ qkv, float* __restrict__ ctx)
{
    extern __shared__ float sm[];
    float* Qs = sm;                       // [64][129]
    float* Ks = Qs + 64 * QS_LD;          // [64][129]
    float* Vs = Ks + 64 * QS_LD;          // [64][128]
    float* Ps = Vs + 64 * 128;            // [64][65]

    const int tid = threadIdx.x;
    const int tx = tid & 15;
    const int ty = tid >> 4;
    const int qt = blockIdx.x;
    const int head = blockIdx.y;
    const int bb = blockIdx.z;
    const int q0 = qt * QT;
    const size_t head_off = (size_t)head * (3 * HDIM);

    // Load Q tile [64][128]
    for (int idx = tid; idx < 64 * 32; idx += 256) {
        int r = idx >> 5;
        int c4 = (idx & 31) * 4;
        const float* src = qkv + ((size_t)(q0 + r) * BATCH + bb) * QKV_N + head_off + c4;
        float4 v = *(const float4*)src;
        float* dst = Qs + r * QS_LD + c4;
        dst[0] = v.x; dst[1] = v.y; dst[2] = v.z; dst[3] = v.w;
    }

    float m_run[4], l_run[4], o[4][8];
#pragma unroll
    for (int i = 0; i < 4; i++) {
        m_run[i] = -1e30f;
        l_run[i] = 0.f;
#pragma unroll
        for (int c = 0; c < 8; c++) o[i][c] = 0.f;
    }

    const float scale = 0.08838834764831845f;  // 1/sqrt(128)

    for (int kt = 0; kt <= qt; kt++) {
        __syncthreads();  // prev PV done with Vs/Ps; Q loads visible on 1st iter

        // Load K,V tiles [64][128]
        const int krow0 = kt * QT;
        for (int idx = tid; idx < 64 * 32; idx += 256) {
            int r = idx >> 5;
            int c4 = (idx & 31) * 4;
            const float* srcK = qkv + ((size_t)(krow0 + r) * BATCH + bb) * QKV_N
                                + head_off + HDIM + c4;
            float4 kv = *(const float4*)srcK;
            float4 vv = *(const float4*)(srcK + HDIM);
            float* dk = Ks + r * QS_LD + c4;
            dk[0] = kv.x; dk[1] = kv.y; dk[2] = kv.z; dk[3] = kv.w;
            *(float4*)(Vs + r * 128 + c4) = vv;
        }
        __syncthreads();

        // S = Q @ K^T (4x4 per thread)
        float sv[4][4];
#pragma unroll
        for (int i = 0; i < 4; i++)
#pragma unroll
            for (int j = 0; j < 4; j++) sv[i][j] = 0.f;

        for (int k = 0; k < 128; k++) {
            float qv[4], kv[4];
#pragma unroll
            for (int i = 0; i < 4; i++) qv[i] = Qs[(ty * 4 + i) * QS_LD + k];
#pragma unroll
            for (int j = 0; j < 4; j++) kv[j] = Ks[(tx * 4 + j) * QS_LD + k];
#pragma unroll
            for (int i = 0; i < 4; i++)
#pragma unroll
                for (int j = 0; j < 4; j++)
                    sv[i][j] += qv[i] * kv[j];
        }

        const bool diag = (kt == qt);
#pragma unroll
        for (int i = 0; i < 4; i++)
#pragma unroll
            for (int j = 0; j < 4; j++) {
                sv[i][j] *= scale;
                if (diag && (krow0 + tx * 4 + j) > (q0 + ty * 4 + i))
                    sv[i][j] = -10000.f;
            }

        // Online softmax per row (reduce across the 16 lanes sharing ty)
#pragma unroll
        for (int i = 0; i < 4; i++) {
            float mloc = sv[i][0];
#pragma unroll
            for (int j = 1; j < 4; j++) mloc = fmaxf(mloc, sv[i][j]);
#pragma unroll
            for (int off = 8; off >= 1; off >>= 1)
                mloc = fmaxf(mloc, __shfl_xor_sync(0xffffffffu, mloc, off));
            float mnew = fmaxf(m_run[i], mloc);
            float corr = __expf(m_run[i] - mnew);
            float psum = 0.f;
#pragma unroll
            for (int j = 0; j < 4; j++) {
                float p = __expf(sv[i][j] - mnew);
                Ps[(ty * 4 + i) * PS_LD + tx * 4 + j] = p;
                psum += p;
            }
#pragma unroll
            for (int off = 8; off >= 1; off >>= 1)
                psum += __shfl_xor_sync(0xffffffffu, psum, off);
            l_run[i] = l_run[i] * corr + psum;
            m_run[i] = mnew;
#pragma unroll
            for (int c = 0; c < 8; c++) o[i][c] *= corr;
        }
        __syncthreads();  // Ps visible

        // O += P @ V
        for (int k = 0; k < QT; k++) {
            float pv[4];
#pragma unroll
            for (int i = 0; i < 4; i++) pv[i] = Ps[(ty * 4 + i) * PS_LD + k];
            float4 v0 = *(const float4*)&Vs[k * 128 + tx * 8];
            float4 v1 = *(const float4*)&Vs[k * 128 + tx * 8 + 4];
            float vr[8] = {v0.x, v0.y, v0.z, v0.w, v1.x, v1.y, v1.z, v1.w};
#pragma unroll
            for (int i = 0; i < 4; i++)
#pragma unroll
                for (int c = 0; c < 8; c++)
                    o[i][c] += pv[i] * vr[c];
        }
    }

    // Epilogue: normalize and write ctx[s, b, head*128 + c]
#pragma unroll
    for (int i = 0; i < 4; i++) {
        float inv = 1.f / l_run[i];
        float4 r0, r1;
        r0.x = o[i][0] * inv; r0.y = o[i][1] * inv;
        r0.z = o[i][2] * inv; r0.w = o[i][3] * inv;
        r1.x = o[i][4] * inv; r1.y = o[i][5] * inv;
        r1.z = o[i][6] * inv; r1.w = o[i][7] * inv;
        float* dst = ctx + ((size_t)(q0 + ty * 4 + i) * BATCH + bb) * HID
                     + head * HDIM + tx * 8;
        *(float4*)(dst + 0) = r0;
        *(float4*)(dst + 4) = r1;
    }
}

// ---------------------------------------------------------------------------
// Inputs (metadata order): hidden_states f32 [2048,2,2048], attention_mask
// (ignored: known causal), w_qkv f32 [6144,2048], b_qkv f32 [6144],
// w_dense f32 [2048,2048], b_dense f32 [2048].
// Output: flatten(output [2048,2,2048]) ++ b_dense [2048].
// ---------------------------------------------------------------------------
extern "C" void kernel_launch(void* const* d_in, const int* in_sizes, int n_in,
                              void* d_out, int out_size)
{
    const float* hs      = (const float*)d_in[0];
    const float* w_qkv   = (const float*)d_in[2];
    const float* b_qkv   = (const float*)d_in[3];
    const float* w_dense = (const float*)d_in[4];
    const float* b_dense = (const float*)d_in[5];
    float* out = (float*)d_out;

    float *qkv_buf, *ctx_buf;
    cudaGetSymbolAddress((void**)&qkv_buf, g_qkv);
    cudaGetSymbolAddress((void**)&ctx_buf, g_ctx);

    cudaFuncSetAttribute(attn_kernel,
                         cudaFuncAttributeMaxDynamicSharedMemorySize,
                         ATTN_SMEM_BYTES);

    // 1) QKV projection: [4096,6144] = hs @ w_qkv^T + b_qkv
    sgemm_nt_kernel<<<dim3(QKV_N / 128, ROWS / 128), 256>>>(
        hs, w_qkv, b_qkv, qkv_buf, ROWS, QKV_N, HID, 1);

    // 2) Causal flash attention -> ctx [4096, 2048]
    attn_kernel<<<dim3(S_LEN / QT, NHEAD, BATCH), 256, ATTN_SMEM_BYTES>>>(
        qkv_buf, ctx_buf);

    // 3) Dense projection: out = ctx @ w_dense^T  (skip_bias_add)
    sgemm_nt_kernel<<<dim3(HID / 128, ROWS / 128), 256>>>(
        ctx_buf, w_dense, nullptr, out, ROWS, HID, HID, 0);

    // 4) b_dense returned separately -> tail of d_out
    if (out_size >= (int)((size_t)ROWS * HID + HID)) {
        cudaMemcpyAsync(out + (size_t)ROWS * HID, b_dense,
                        HID * sizeof(float), cudaMemcpyDeviceToDevice);
    }
}

// round 3
// speedup vs baseline: 3.3261x; 3.3261x over previous
#include <cuda_runtime.h>
#include <math.h>
#include <stdint.h>

#define S_LEN 2048
#define BATCH 2
#define HID 2048
#define NHEAD 16
#define HDIM 128
#define QKV_N 6144
#define ROWS 4096

// ---------------- scratch (device globals; allocation forbidden) -----------
__device__ uint32_t g_hs_t[(size_t)ROWS * HID];      // tf32 bits of hidden_states
__device__ uint32_t g_wqkv_t[(size_t)QKV_N * HID];   // tf32 bits of w_qkv
__device__ uint32_t g_wd_t[(size_t)HID * HID];       // tf32 bits of w_dense
__device__ float    g_qkv[(size_t)ROWS * QKV_N];     // fp32 qkv output
__device__ uint32_t g_ctx_t[(size_t)ROWS * HID];     // tf32 bits of ctx

// ---------------- helpers --------------------------------------------------
__device__ __forceinline__ uint32_t f2tf(float x) {
    uint32_t r; asm("cvt.rna.tf32.f32 %0, %1;" : "=r"(r) : "f"(x)); return r;
}
__device__ __forceinline__ void mma8(float* c, const uint32_t* a, uint32_t b0, uint32_t b1) {
    asm volatile("mma.sync.aligned.m16n8k8.row.col.f32.tf32.tf32.f32 "
        "{%0,%1,%2,%3},{%4,%5,%6,%7},{%8,%9},{%0,%1,%2,%3};"
        : "+f"(c[0]), "+f"(c[1]), "+f"(c[2]), "+f"(c[3])
        : "r"(a[0]), "r"(a[1]), "r"(a[2]), "r"(a[3]), "r"(b0), "r"(b1));
}
__device__ __forceinline__ void cp16(uint32_t saddr, const void* gptr) {
    asm volatile("cp.async.cg.shared.global [%0], [%1], 16;" :: "r"(saddr), "l"(gptr));
}

// ---------------- fp32 -> tf32 conversion kernel ---------------------------
__global__ void cvt_tf32_kernel(const float4* __restrict__ in, uint4* __restrict__ out, int n4) {
    int i = blockIdx.x * blockDim.x + threadIdx.x;
    if (i < n4) {
        float4 v = in[i];
        uint4 o;
        o.x = f2tf(v.x); o.y = f2tf(v.y); o.z = f2tf(v.z); o.w = f2tf(v.w);
        out[i] = o;
    }
}

// ---------------- tf32 GEMM: C[m,n] = A[m,:] . B[n,:] (+bias) --------------
// A: [M,K] tf32 bits row-major. B: [N,K] tf32 bits row-major. C fp32.
// Block 128x256, BK=32, 256 threads (8 warps as 2x4, each 64x64 warp tile).
#define GBM 128
#define GBN 256
#define GBK 32
#define ALD 36
#define BLD 36
#define ASZ (GBM * ALD)                 // 4608 words
#define BSZ (GBN * BLD)                 // 9216 words
#define GEMM_SMEM_BYTES (2 * (ASZ + BSZ) * 4)   // 110592

__global__ __launch_bounds__(256, 1)
void gemm_tf32(const uint32_t* __restrict__ A, const uint32_t* __restrict__ B,
               const float* __restrict__ bias, float* __restrict__ C,
               int M, int N, int K, int add_bias)
{
    extern __shared__ uint32_t sm[];
    uint32_t* Abuf[2] = { sm, sm + ASZ + BSZ };
    uint32_t* Bbuf[2] = { sm + ASZ, sm + 2 * ASZ + BSZ };

    const int tid = threadIdx.x;
    const int lane = tid & 31, warp = tid >> 5;
    const int g = lane >> 2, tg = lane & 3;
    const int wm = warp >> 2, wn = warp & 3;
    const int m0 = blockIdx.y * GBM, n0 = blockIdx.x * GBN;

    float c[4][8][4];
#pragma unroll
    for (int i = 0; i < 4; i++)
#pragma unroll
        for (int j = 0; j < 8; j++)
#pragma unroll
            for (int q = 0; q < 4; q++) c[i][j][q] = 0.f;

    auto load_tile = [&](int k0, int buf) {
        uint32_t ab = (uint32_t)__cvta_generic_to_shared(Abuf[buf]);
        uint32_t bbs = (uint32_t)__cvta_generic_to_shared(Bbuf[buf]);
#pragma unroll
        for (int t = 0; t < 4; t++) {                   // A: 128x32 = 1024 16B chunks
            int fid = tid + 256 * t;
            int r = fid >> 3, c4 = (fid & 7) * 4;
            cp16(ab + (uint32_t)(r * ALD + c4) * 4, A + (size_t)(m0 + r) * K + k0 + c4);
        }
#pragma unroll
        for (int t = 0; t < 8; t++) {                   // B: 256x32 = 2048 chunks
            int fid = tid + 256 * t;
            int r = fid >> 3, c4 = (fid & 7) * 4;
            cp16(bbs + (uint32_t)(r * BLD + c4) * 4, B + (size_t)(n0 + r) * K + k0 + c4);
        }
        asm volatile("cp.async.commit_group;");
    };

    load_tile(0, 0);
    const int NI = K / GBK;
    int buf = 0;
    for (int it = 0; it < NI; it++) {
        asm volatile("cp.async.wait_group 0;");
        __syncthreads();
        if (it + 1 < NI) load_tile((it + 1) * GBK, buf ^ 1);

        const uint32_t* Ab = Abuf[buf];
        const uint32_t* Bb = Bbuf[buf];
#pragma unroll
        for (int kk = 0; kk < 4; kk++) {
            uint32_t a[4][4];
#pragma unroll
            for (int i = 0; i < 4; i++) {
                const uint32_t* p = Ab + (wm * 64 + i * 16 + g) * ALD + kk * 8 + tg;
                a[i][0] = p[0]; a[i][1] = p[8 * ALD]; a[i][2] = p[4]; a[i][3] = p[8 * ALD + 4];
            }
#pragma unroll
            for (int j = 0; j < 8; j++) {
                const uint32_t* p = Bb + (wn * 64 + j * 8 + g) * BLD + kk * 8 + tg;
                uint32_t b0 = p[0], b1 = p[4];
#pragma unroll
                for (int i = 0; i < 4; i++) mma8(c[i][j], a[i], b0, b1);
            }
        }
        buf ^= 1;
    }

#pragma unroll
    for (int i = 0; i < 4; i++) {
        int row = m0 + wm * 64 + i * 16 + g;
#pragma unroll
        for (int j = 0; j < 8; j++) {
            int col = n0 + wn * 64 + j * 8 + 2 * tg;
            float b0 = add_bias ? bias[col] : 0.f;
            float b1 = add_bias ? bias[col + 1] : 0.f;
            float2 v0 = { c[i][j][0] + b0, c[i][j][1] + b1 };
            float2 v1 = { c[i][j][2] + b0, c[i][j][3] + b1 };
            *(float2*)(C + (size_t)row * N + col) = v0;
            *(float2*)(C + (size_t)(row + 8) * N + col) = v1;
        }
    }
}

// ---------------- tf32 flash attention -------------------------------------
// Q tile 128 rows, K/V tiles 64 rows, head dim 128. 8 warps; warp owns 16 q-rows.
#define ATT_Q_LD 132
#define ATT_K_LD 132
#define ATT_V_LD 136
#define ATT_P_LD 68
#define ATT_SMEM_WORDS (128 * ATT_Q_LD + 64 * ATT_K_LD + 64 * ATT_V_LD + 128 * ATT_P_LD)
#define ATT_SMEM_BYTES (ATT_SMEM_WORDS * 4)   // 171008

__global__ __launch_bounds__(256, 1)
void attn_tf32(const float* __restrict__ qkv, uint32_t* __restrict__ ctx)
{
    extern __shared__ uint32_t sm[];
    uint32_t* Qs = sm;
    uint32_t* Ks = Qs + 128 * ATT_Q_LD;
    uint32_t* Vs = Ks + 64 * ATT_K_LD;
    uint32_t* Ps = Vs + 64 * ATT_V_LD;

    const int tid = threadIdx.x, lane = tid & 31, warp = tid >> 5;
    const int g = lane >> 2, tg = lane & 3;
    const int qt = gridDim.x - 1 - blockIdx.x;   // heavy tiles first
    const int head = blockIdx.y, bb = blockIdx.z;
    const int q0 = qt * 128;
    const size_t hoff = (size_t)head * (3 * HDIM);

    // Load this warp's 16 Q rows (tf32-converted)
#pragma unroll
    for (int t = 0; t < 16; t++) {
        const float* src = qkv + ((size_t)(q0 + warp * 16 + t) * BATCH + bb) * QKV_N + hoff + lane * 4;
        float4 v = *(const float4*)src;
        uint4 u; u.x = f2tf(v.x); u.y = f2tf(v.y); u.z = f2tf(v.z); u.w = f2tf(v.w);
        *(uint4*)(Qs + (warp * 16 + t) * ATT_Q_LD + lane * 4) = u;
    }
    __syncwarp();

    float o[16][4];
#pragma unroll
    for (int j = 0; j < 16; j++)
#pragma unroll
        for (int q = 0; q < 4; q++) o[j][q] = 0.f;
    float m0r = -1e30f, m1r = -1e30f, l0r = 0.f, l1r = 0.f;
    const float scale = 0.08838834764831845f;   // 1/sqrt(128)

    const int nkt = 2 * qt + 2;
    for (int kt = 0; kt < nkt; kt++) {
        __syncthreads();   // prior iter done reading Ks/Vs/Ps
        const int kr0 = kt * 64;
#pragma unroll
        for (int t = 0; t < 8; t++) {      // K,V tiles 64x128 each
            int fid = tid + 256 * t;
            int r = fid >> 5, c4 = (fid & 31) * 4;
            const float* s = qkv + ((size_t)(kr0 + r) * BATCH + bb) * QKV_N + hoff + HDIM + c4;
            float4 kv = *(const float4*)s;
            float4 vv = *(const float4*)(s + HDIM);
            uint4 uk; uk.x = f2tf(kv.x); uk.y = f2tf(kv.y); uk.z = f2tf(kv.z); uk.w = f2tf(kv.w);
            uint4 uv; uv.x = f2tf(vv.x); uv.y = f2tf(vv.y); uv.z = f2tf(vv.z); uv.w = f2tf(vv.w);
            *(uint4*)(Ks + r * ATT_K_LD + c4) = uk;
            *(uint4*)(Vs + r * ATT_V_LD + c4) = uv;
        }
        __syncthreads();

        const int rowg = q0 + warp * 16 + g;
        const bool active = (kr0 <= q0 + warp * 16 + 15);
        if (active) {
            // S = Q @ K^T  (warp: 16 rows x 64 cols)
            float s[8][4];
#pragma unroll
            for (int j = 0; j < 8; j++)
#pragma unroll
                for (int q = 0; q < 4; q++) s[j][q] = 0.f;
#pragma unroll
            for (int kk = 0; kk < 16; kk++) {
                uint32_t a[4];
                const uint32_t* qp = Qs + (warp * 16 + g) * ATT_Q_LD + kk * 8 + tg;
                a[0] = qp[0]; a[1] = qp[8 * ATT_Q_LD]; a[2] = qp[4]; a[3] = qp[8 * ATT_Q_LD + 4];
#pragma unroll
                for (int j = 0; j < 8; j++) {
                    const uint32_t* kp = Ks + (j * 8 + g) * ATT_K_LD + kk * 8 + tg;
                    mma8(s[j], a, kp[0], kp[4]);
                }
            }
            // scale + causal mask
#pragma unroll
            for (int j = 0; j < 8; j++) {
                int cb = kr0 + j * 8 + 2 * tg;
                s[j][0] = (cb     > rowg)     ? -10000.f : s[j][0] * scale;
                s[j][1] = (cb + 1 > rowg)     ? -10000.f : s[j][1] * scale;
                s[j][2] = (cb     > rowg + 8) ? -10000.f : s[j][2] * scale;
                s[j][3] = (cb + 1 > rowg + 8) ? -10000.f : s[j][3] * scale;
            }
            // online softmax, row 0 (c0,c1) and row 1 (c2,c3)
            {
                float ml = -1e30f;
#pragma unroll
                for (int j = 0; j < 8; j++) ml = fmaxf(ml, fmaxf(s[j][0], s[j][1]));
                ml = fmaxf(ml, __shfl_xor_sync(0xffffffffu, ml, 1));
                ml = fmaxf(ml, __shfl_xor_sync(0xffffffffu, ml, 2));
                float mn = fmaxf(m0r, ml);
                float corr = __expf(m0r - mn);
                float ps = 0.f;
#pragma unroll
                for (int j = 0; j < 8; j++) {
                    s[j][0] = __expf(s[j][0] - mn);
                    s[j][1] = __expf(s[j][1] - mn);
                    ps += s[j][0] + s[j][1];
                }
                ps += __shfl_xor_sync(0xffffffffu, ps, 1);
                ps += __shfl_xor_sync(0xffffffffu, ps, 2);
                l0r = l0r * corr + ps; m0r = mn;
#pragma unroll
                for (int j = 0; j < 16; j++) { o[j][0] *= corr; o[j][1] *= corr; }
            }
            {
                float ml = -1e30f;
#pragma unroll
                for (int j = 0; j < 8; j++) ml = fmaxf(ml, fmaxf(s[j][2], s[j][3]));
                ml = fmaxf(ml, __shfl_xor_sync(0xffffffffu, ml, 1));
                ml = fmaxf(ml, __shfl_xor_sync(0xffffffffu, ml, 2));
                float mn = fmaxf(m1r, ml);
                float corr = __expf(m1r - mn);
                float ps = 0.f;
#pragma unroll
                for (int j = 0; j < 8; j++) {
                    s[j][2] = __expf(s[j][2] - mn);
                    s[j][3] = __expf(s[j][3] - mn);
                    ps += s[j][2] + s[j][3];
                }
                ps += __shfl_xor_sync(0xffffffffu, ps, 1);
                ps += __shfl_xor_sync(0xffffffffu, ps, 2);
                l1r = l1r * corr + ps; m1r = mn;
#pragma unroll
                for (int j = 0; j < 16; j++) { o[j][2] *= corr; o[j][3] *= corr; }
            }
            // P -> smem (tf32) for re-fragmenting
#pragma unroll
            for (int j = 0; j < 8; j++) {
                uint32_t* p0 = Ps + (warp * 16 + g) * ATT_P_LD + j * 8 + 2 * tg;
                p0[0] = f2tf(s[j][0]); p0[1] = f2tf(s[j][1]);
                uint32_t* p1 = p0 + 8 * ATT_P_LD;
                p1[0] = f2tf(s[j][2]); p1[1] = f2tf(s[j][3]);
            }
        }
        __syncwarp();   // warp reads only its own P rows
        if (active) {
            // O += P @ V  (16 rows x 128 cols, k=64)
#pragma unroll
            for (int kk = 0; kk < 8; kk++) {
                uint32_t a[4];
                const uint32_t* pp = Ps + (warp * 16 + g) * ATT_P_LD + kk * 8 + tg;
                a[0] = pp[0]; a[1] = pp[8 * ATT_P_LD]; a[2] = pp[4]; a[3] = pp[8 * ATT_P_LD + 4];
#pragma unroll
                for (int j = 0; j < 16; j++) {
                    const uint32_t* vp = Vs + (kk * 8 + tg) * ATT_V_LD + j * 8 + g;
                    mma8(o[j], a, vp[0], vp[4 * ATT_V_LD]);
                }
            }
        }
    }

    // epilogue: normalize, write ctx as tf32 bits
    const float i0 = 1.f / l0r, i1 = 1.f / l1r;
    const int r0g = q0 + warp * 16 + g;
#pragma unroll
    for (int j = 0; j < 16; j++) {
        int col = head * HDIM + j * 8 + 2 * tg;
        uint2 v0 = { f2tf(o[j][0] * i0), f2tf(o[j][1] * i0) };
        uint2 v1 = { f2tf(o[j][2] * i1), f2tf(o[j][3] * i1) };
        *(uint2*)(ctx + ((size_t)r0g * BATCH + bb) * HID + col) = v0;
        *(uint2*)(ctx + ((size_t)(r0g + 8) * BATCH + bb) * HID + col) = v1;
    }
}

// ---------------------------------------------------------------------------
extern "C" void kernel_launch(void* const* d_in, const int* in_sizes, int n_in,
                              void* d_out, int out_size)
{
    const float* hs      = (const float*)d_in[0];
    const float* w_qkv   = (const float*)d_in[2];
    const float* b_qkv   = (const float*)d_in[3];
    const float* w_dense = (const float*)d_in[4];
    const float* b_dense = (const float*)d_in[5];
    float* out = (float*)d_out;

    uint32_t *hs_t, *wqkv_t, *wd_t, *ctx_t;
    float* qkv_buf;
    cudaGetSymbolAddress((void**)&hs_t, g_hs_t);
    cudaGetSymbolAddress((void**)&wqkv_t, g_wqkv_t);
    cudaGetSymbolAddress((void**)&wd_t, g_wd_t);
    cudaGetSymbolAddress((void**)&qkv_buf, g_qkv);
    cudaGetSymbolAddress((void**)&ctx_t, g_ctx_t);

    cudaFuncSetAttribute(gemm_tf32, cudaFuncAttributeMaxDynamicSharedMemorySize, GEMM_SMEM_BYTES);
    cudaFuncSetAttribute(attn_tf32, cudaFuncAttributeMaxDynamicSharedMemorySize, ATT_SMEM_BYTES);

    // 0) pre-round GEMM operands to tf32 (rna)
    {
        int n4;
        n4 = ROWS * HID / 4;
        cvt_tf32_kernel<<<(n4 + 255) / 256, 256>>>((const float4*)hs, (uint4*)hs_t, n4);
        n4 = QKV_N * HID / 4;
        cvt_tf32_kernel<<<(n4 + 255) / 256, 256>>>((const float4*)w_qkv, (uint4*)wqkv_t, n4);
        n4 = HID * HID / 4;
        cvt_tf32_kernel<<<(n4 + 255) / 256, 256>>>((const float4*)w_dense, (uint4*)wd_t, n4);
    }

    // 1) QKV projection: [4096,6144] = hs @ w_qkv^T + b_qkv
    gemm_tf32<<<dim3(QKV_N / GBN, ROWS / GBM), 256, GEMM_SMEM_BYTES>>>(
        hs_t, wqkv_t, b_qkv, qkv_buf, ROWS, QKV_N, HID, 1);

    // 2) causal flash attention -> ctx (tf32 bits)
    attn_tf32<<<dim3(S_LEN / 128, NHEAD, BATCH), 256, ATT_SMEM_BYTES>>>(qkv_buf, ctx_t);

    // 3) dense projection: out = ctx @ w_dense^T (skip_bias_add)
    gemm_tf32<<<dim3(HID / GBN, ROWS / GBM), 256, GEMM_SMEM_BYTES>>>(
        ctx_t, wd_t, nullptr, out, ROWS, HID, HID, 0);

    // 4) b_dense returned separately -> tail of d_out
    if (out_size >= (int)((size_t)ROWS * HID + HID)) {
        cudaMemcpyAsync(out + (size_t)ROWS * HID, b_dense,
                        HID * sizeof(float), cudaMemcpyDeviceToDevice);
    }
}

// round 5
// speedup vs baseline: 3.7928x; 1.1403x over previous
#include <cuda_runtime.h>
#include <math.h>
#include <stdint.h>

#define S_LEN 2048
#define BATCH 2
#define HID 2048
#define NHEAD 16
#define HDIM 128
#define QKV_N 6144
#define ROWS 4096

// ---------------- scratch (device globals; allocation forbidden) -----------
__device__ uint32_t g_hs_t[(size_t)ROWS * HID];      // tf32 bits of hidden_states
__device__ uint32_t g_wqkv_t[(size_t)QKV_N * HID];   // tf32 bits of w_qkv
__device__ uint32_t g_wd_t[(size_t)HID * HID];       // tf32 bits of w_dense
__device__ float    g_qkv[(size_t)ROWS * QKV_N];     // fp32 qkv output
__device__ uint32_t g_ctx_t[(size_t)ROWS * HID];     // tf32 bits of ctx

// ---------------- helpers --------------------------------------------------
__device__ __forceinline__ uint32_t f2tf(float x) {
    uint32_t r; asm("cvt.rna.tf32.f32 %0, %1;" : "=r"(r) : "f"(x)); return r;
}
__device__ __forceinline__ void mma8(float* c, const uint32_t* a, uint32_t b0, uint32_t b1) {
    asm volatile("mma.sync.aligned.m16n8k8.row.col.f32.tf32.tf32.f32 "
        "{%0,%1,%2,%3},{%4,%5,%6,%7},{%8,%9},{%0,%1,%2,%3};"
        : "+f"(c[0]), "+f"(c[1]), "+f"(c[2]), "+f"(c[3])
        : "r"(a[0]), "r"(a[1]), "r"(a[2]), "r"(a[3]), "r"(b0), "r"(b1));
}
__device__ __forceinline__ void cp16(uint32_t saddr, const void* gptr) {
    asm volatile("cp.async.cg.shared.global [%0], [%1], 16;" :: "r"(saddr), "l"(gptr));
}

// ---------------- fp32 -> tf32 conversion kernel ---------------------------
__global__ void cvt_tf32_kernel(const float4* __restrict__ in, uint4* __restrict__ out, int n4) {
    int i = blockIdx.x * blockDim.x + threadIdx.x;
    if (i < n4) {
        float4 v = in[i];
        uint4 o;
        o.x = f2tf(v.x); o.y = f2tf(v.y); o.z = f2tf(v.z); o.w = f2tf(v.w);
        out[i] = o;
    }
}

// ---------------- tf32 GEMM: C[m,n] = A[m,:] . B[n,:] (+bias) --------------
// A: [M,K] tf32 bits row-major. B: [N,K] tf32 bits row-major. C fp32.
// Block 128x128, BK=32, 3-stage cp.async pipeline, 256 threads (8 warps as
// 2x4, each with a 64x32 warp tile -> 64 C regs/thread, no spills, 2 CTA/SM).
#define GBM 128
#define GBN 128
#define GBK 32
#define SLD 36
#define TSZ (128 * SLD)                         // words per operand tile
#define GEMM_SMEM_BYTES (3 * 2 * TSZ * 4)       // 110592

__global__ __launch_bounds__(256, 2)
void gemm_tf32(const uint32_t* __restrict__ A, const uint32_t* __restrict__ B,
               const float* __restrict__ bias, float* __restrict__ C,
               int M, int N, int K, int add_bias)
{
    extern __shared__ uint32_t sm[];

    const int tid = threadIdx.x;
    const int lane = tid & 31, warp = tid >> 5;
    const int g = lane >> 2, tg = lane & 3;
    const int wm = warp >> 2, wn = warp & 3;     // 2 x 4 warps
    const int m0 = blockIdx.y * GBM, n0 = blockIdx.x * GBN;

    float c[4][4][4];
#pragma unroll
    for (int i = 0; i < 4; i++)
#pragma unroll
        for (int j = 0; j < 4; j++)
#pragma unroll
            for (int q = 0; q < 4; q++) c[i][j][q] = 0.f;

    auto load_stage = [&](int it, int buf) {
        uint32_t* Ab = sm + buf * 2 * TSZ;
        uint32_t* Bb = Ab + TSZ;
        uint32_t ab = (uint32_t)__cvta_generic_to_shared(Ab);
        uint32_t bb = (uint32_t)__cvta_generic_to_shared(Bb);
        const int k0 = it * GBK;
#pragma unroll
        for (int t = 0; t < 4; t++) {            // 128 rows x 8 16B-chunks
            int fid = tid + 256 * t;
            int r = fid >> 3, c4 = (fid & 7) * 4;
            cp16(ab + (uint32_t)(r * SLD + c4) * 4, A + (size_t)(m0 + r) * K + k0 + c4);
            cp16(bb + (uint32_t)(r * SLD + c4) * 4, B + (size_t)(n0 + r) * K + k0 + c4);
        }
        asm volatile("cp.async.commit_group;" ::: "memory");
    };

    const int NI = K / GBK;
    load_stage(0, 0);
    load_stage(1, 1);

    for (int it = 0; it < NI; it++) {
        asm volatile("cp.async.wait_group 1;" ::: "memory");
        __syncthreads();
        if (it + 2 < NI) load_stage(it + 2, (it + 2) % 3);

        const uint32_t* Ab = sm + (it % 3) * 2 * TSZ;
        const uint32_t* Bb = Ab + TSZ;
#pragma unroll
        for (int kk = 0; kk < 4; kk++) {
            uint32_t a[4][4];
#pragma unroll
            for (int i = 0; i < 4; i++) {
                const uint32_t* p = Ab + (wm * 64 + i * 16 + g) * SLD + kk * 8 + tg;
                a[i][0] = p[0]; a[i][1] = p[8 * SLD]; a[i][2] = p[4]; a[i][3] = p[8 * SLD + 4];
            }
#pragma unroll
            for (int j = 0; j < 4; j++) {
                const uint32_t* p = Bb + (wn * 32 + j * 8 + g) * SLD + kk * 8 + tg;
                uint32_t b0 = p[0], b1 = p[4];
#pragma unroll
                for (int i = 0; i < 4; i++) mma8(c[i][j], a[i], b0, b1);
            }
        }
        __syncthreads();
    }

#pragma unroll
    for (int i = 0; i < 4; i++) {
        int row = m0 + wm * 64 + i * 16 + g;
#pragma unroll
        for (int j = 0; j < 4; j++) {
            int col = n0 + wn * 32 + j * 8 + 2 * tg;
            float b0 = add_bias ? bias[col] : 0.f;
            float b1 = add_bias ? bias[col + 1] : 0.f;
            float2 v0 = { c[i][j][0] + b0, c[i][j][1] + b1 };
            float2 v1 = { c[i][j][2] + b0, c[i][j][3] + b1 };
            *(float2*)(C + (size_t)row * N + col) = v0;
            *(float2*)(C + (size_t)(row + 8) * N + col) = v1;
        }
    }
}

// ---------------- tf32 flash attention -------------------------------------
// Q tile 128 rows, K/V tiles 64 rows, head dim 128. 8 warps; warp owns 16 q-rows.
#define ATT_Q_LD 132
#define ATT_K_LD 132
#define ATT_V_LD 136
#define ATT_P_LD 68
#define ATT_SMEM_WORDS (128 * ATT_Q_LD + 64 * ATT_K_LD + 64 * ATT_V_LD + 128 * ATT_P_LD)
#define ATT_SMEM_BYTES (ATT_SMEM_WORDS * 4)   // 171008

__global__ __launch_bounds__(256, 1)
void attn_tf32(const float* __restrict__ qkv, uint32_t* __restrict__ ctx)
{
    extern __shared__ uint32_t sm[];
    uint32_t* Qs = sm;
    uint32_t* Ks = Qs + 128 * ATT_Q_LD;
    uint32_t* Vs = Ks + 64 * ATT_K_LD;
    uint32_t* Ps = Vs + 64 * ATT_V_LD;

    const int tid = threadIdx.x, lane = tid & 31, warp = tid >> 5;
    const int g = lane >> 2, tg = lane & 3;
    const int qt = gridDim.x - 1 - blockIdx.x;   // heavy tiles first
    const int head = blockIdx.y, bb = blockIdx.z;
    const int q0 = qt * 128;
    const size_t hoff = (size_t)head * (3 * HDIM);

#pragma unroll
    for (int t = 0; t < 16; t++) {
        const float* src = qkv + ((size_t)(q0 + warp * 16 + t) * BATCH + bb) * QKV_N + hoff + lane * 4;
        float4 v = *(const float4*)src;
        uint4 u; u.x = f2tf(v.x); u.y = f2tf(v.y); u.z = f2tf(v.z); u.w = f2tf(v.w);
        *(uint4*)(Qs + (warp * 16 + t) * ATT_Q_LD + lane * 4) = u;
    }
    __syncwarp();

    float o[16][4];
#pragma unroll
    for (int j = 0; j < 16; j++)
#pragma unroll
        for (int q = 0; q < 4; q++) o[j][q] = 0.f;
    float m0r = -1e30f, m1r = -1e30f, l0r = 0.f, l1r = 0.f;
    const float scale = 0.08838834764831845f;   // 1/sqrt(128)

    const int nkt = 2 * qt + 2;
    for (int kt = 0; kt < nkt; kt++) {
        __syncthreads();   // prior iter done reading Ks/Vs/Ps
        const int kr0 = kt * 64;
#pragma unroll
        for (int t = 0; t < 8; t++) {      // K,V tiles 64x128 each
            int fid = tid + 256 * t;
            int r = fid >> 5, c4 = (fid & 31) * 4;
            const float* s = qkv + ((size_t)(kr0 + r) * BATCH + bb) * QKV_N + hoff + HDIM + c4;
            float4 kv = *(const float4*)s;
            float4 vv = *(const float4*)(s + HDIM);
            uint4 uk; uk.x = f2tf(kv.x); uk.y = f2tf(kv.y); uk.z = f2tf(kv.z); uk.w = f2tf(kv.w);
            uint4 uv; uv.x = f2tf(vv.x); uv.y = f2tf(vv.y); uv.z = f2tf(vv.z); uv.w = f2tf(vv.w);
            *(uint4*)(Ks + r * ATT_K_LD + c4) = uk;
            *(uint4*)(Vs + r * ATT_V_LD + c4) = uv;
        }
        __syncthreads();

        const int rowg = q0 + warp * 16 + g;
        const bool active = (kr0 <= q0 + warp * 16 + 15);
        if (active) {
            float s[8][4];
#pragma unroll
            for (int j = 0; j < 8; j++)
#pragma unroll
                for (int q = 0; q < 4; q++) s[j][q] = 0.f;
#pragma unroll
            for (int kk = 0; kk < 16; kk++) {
                uint32_t a[4];
                const uint32_t* qp = Qs + (warp * 16 + g) * ATT_Q_LD + kk * 8 + tg;
                a[0] = qp[0]; a[1] = qp[8 * ATT_Q_LD]; a[2] = qp[4]; a[3] = qp[8 * ATT_Q_LD + 4];
#pragma unroll
                for (int j = 0; j < 8; j++) {
                    const uint32_t* kp = Ks + (j * 8 + g) * ATT_K_LD + kk * 8 + tg;
                    mma8(s[j], a, kp[0], kp[4]);
                }
            }
#pragma unroll
            for (int j = 0; j < 8; j++) {
                int cb = kr0 + j * 8 + 2 * tg;
                s[j][0] = (cb     > rowg)     ? -10000.f : s[j][0] * scale;
                s[j][1] = (cb + 1 > rowg)     ? -10000.f : s[j][1] * scale;
                s[j][2] = (cb     > rowg + 8) ? -10000.f : s[j][2] * scale;
                s[j][3] = (cb + 1 > rowg + 8) ? -10000.f : s[j][3] * scale;
            }
            {
                float ml = -1e30f;
#pragma unroll
                for (int j = 0; j < 8; j++) ml = fmaxf(ml, fmaxf(s[j][0], s[j][1]));
                ml = fmaxf(ml, __shfl_xor_sync(0xffffffffu, ml, 1));
                ml = fmaxf(ml, __shfl_xor_sync(0xffffffffu, ml, 2));
                float mn = fmaxf(m0r, ml);
                float corr = __expf(m0r - mn);
                float ps = 0.f;
#pragma unroll
                for (int j = 0; j < 8; j++) {
                    s[j][0] = __expf(s[j][0] - mn);
                    s[j][1] = __expf(s[j][1] - mn);
                    ps += s[j][0] + s[j][1];
                }
                ps += __shfl_xor_sync(0xffffffffu, ps, 1);
                ps += __shfl_xor_sync(0xffffffffu, ps, 2);
                l0r = l0r * corr + ps; m0r = mn;
#pragma unroll
                for (int j = 0; j < 16; j++) { o[j][0] *= corr; o[j][1] *= corr; }
            }
            {
                float ml = -1e30f;
#pragma unroll
                for (int j = 0; j < 8; j++) ml = fmaxf(ml, fmaxf(s[j][2], s[j][3]));
                ml = fmaxf(ml, __shfl_xor_sync(0xffffffffu, ml, 1));
                ml = fmaxf(ml, __shfl_xor_sync(0xffffffffu, ml, 2));
                float mn = fmaxf(m1r, ml);
                float corr = __expf(m1r - mn);
                float ps = 0.f;
#pragma unroll
                for (int j = 0; j < 8; j++) {
                    s[j][2] = __expf(s[j][2] - mn);
                    s[j][3] = __expf(s[j][3] - mn);
                    ps += s[j][2] + s[j][3];
                }
                ps += __shfl_xor_sync(0xffffffffu, ps, 1);
                ps += __shfl_xor_sync(0xffffffffu, ps, 2);
                l1r = l1r * corr + ps; m1r = mn;
#pragma unroll
                for (int j = 0; j < 16; j++) { o[j][2] *= corr; o[j][3] *= corr; }
            }
#pragma unroll
            for (int j = 0; j < 8; j++) {
                uint32_t* p0 = Ps + (warp * 16 + g) * ATT_P_LD + j * 8 + 2 * tg;
                p0[0] = f2tf(s[j][0]); p0[1] = f2tf(s[j][1]);
                uint32_t* p1 = p0 + 8 * ATT_P_LD;
                p1[0] = f2tf(s[j][2]); p1[1] = f2tf(s[j][3]);
            }
        }
        __syncwarp();   // warp reads only its own P rows
        if (active) {
#pragma unroll
            for (int kk = 0; kk < 8; kk++) {
                uint32_t a[4];
                const uint32_t* pp = Ps + (warp * 16 + g) * ATT_P_LD + kk * 8 + tg;
                a[0] = pp[0]; a[1] = pp[8 * ATT_P_LD]; a[2] = pp[4]; a[3] = pp[8 * ATT_P_LD + 4];
#pragma unroll
                for (int j = 0; j < 16; j++) {
                    const uint32_t* vp = Vs + (kk * 8 + tg) * ATT_V_LD + j * 8 + g;
                    mma8(o[j], a, vp[0], vp[4 * ATT_V_LD]);
                }
            }
        }
    }

    const float i0 = 1.f / l0r, i1 = 1.f / l1r;
    const int r0g = q0 + warp * 16 + g;
#pragma unroll
    for (int j = 0; j < 16; j++) {
        int col = head * HDIM + j * 8 + 2 * tg;
        uint2 v0 = { f2tf(o[j][0] * i0), f2tf(o[j][1] * i0) };
        uint2 v1 = { f2tf(o[j][2] * i1), f2tf(o[j][3] * i1) };
        *(uint2*)(ctx + ((size_t)r0g * BATCH + bb) * HID + col) = v0;
        *(uint2*)(ctx + ((size_t)(r0g + 8) * BATCH + bb) * HID + col) = v1;
    }
}

// ---------------------------------------------------------------------------
extern "C" void kernel_launch(void* const* d_in, const int* in_sizes, int n_in,
                              void* d_out, int out_size)
{
    const float* hs      = (const float*)d_in[0];
    const float* w_qkv   = (const float*)d_in[2];
    const float* b_qkv   = (const float*)d_in[3];
    const float* w_dense = (const float*)d_in[4];
    const float* b_dense = (const float*)d_in[5];
    float* out = (float*)d_out;

    uint32_t *hs_t, *wqkv_t, *wd_t, *ctx_t;
    float* qkv_buf;
    cudaGetSymbolAddress((void**)&hs_t, g_hs_t);
    cudaGetSymbolAddress((void**)&wqkv_t, g_wqkv_t);
    cudaGetSymbolAddress((void**)&wd_t, g_wd_t);
    cudaGetSymbolAddress((void**)&qkv_buf, g_qkv);
    cudaGetSymbolAddress((void**)&ctx_t, g_ctx_t);

    cudaFuncSetAttribute(gemm_tf32, cudaFuncAttributeMaxDynamicSharedMemorySize, GEMM_SMEM_BYTES);
    cudaFuncSetAttribute(attn_tf32, cudaFuncAttributeMaxDynamicSharedMemorySize, ATT_SMEM_BYTES);

    // 0) pre-round GEMM operands to tf32 (rna)
    {
        int n4;
        n4 = ROWS * HID / 4;
        cvt_tf32_kernel<<<(n4 + 255) / 256, 256>>>((const float4*)hs, (uint4*)hs_t, n4);
        n4 = QKV_N * HID / 4;
        cvt_tf32_kernel<<<(n4 + 255) / 256, 256>>>((const float4*)w_qkv, (uint4*)wqkv_t, n4);
        n4 = HID * HID / 4;
        cvt_tf32_kernel<<<(n4 + 255) / 256, 256>>>((const float4*)w_dense, (uint4*)wd_t, n4);
    }

    // 1) QKV projection: [4096,6144] = hs @ w_qkv^T + b_qkv
    gemm_tf32<<<dim3(QKV_N / GBN, ROWS / GBM), 256, GEMM_SMEM_BYTES>>>(
        hs_t, wqkv_t, b_qkv, qkv_buf, ROWS, QKV_N, HID, 1);

    // 2) causal flash attention -> ctx (tf32 bits)
    attn_tf32<<<dim3(S_LEN / 128, NHEAD, BATCH), 256, ATT_SMEM_BYTES>>>(qkv_buf, ctx_t);

    // 3) dense projection: out = ctx @ w_dense^T (skip_bias_add)
    gemm_tf32<<<dim3(HID / GBN, ROWS / GBM), 256, GEMM_SMEM_BYTES>>>(
        ctx_t, wd_t, nullptr, out, ROWS, HID, HID, 0);

    // 4) b_dense returned separately -> tail of d_out
    if (out_size >= (int)((size_t)ROWS * HID + HID)) {
        cudaMemcpyAsync(out + (size_t)ROWS * HID, b_dense,
                        HID * sizeof(float), cudaMemcpyDeviceToDevice);
    }
}